// round 14
// baseline (speedup 1.0000x reference)
#include <cuda_runtime.h>
#include <cuda_bf16.h>
#include <cstdint>
#include <cstddef>
#include <math.h>

#define D 512
#define LSEQ 8192
#define MTOK 65536
#define CHUNK 16384   // rows per pipeline chunk (2 batches)

// ---------------- scratch (static __device__, no allocs) ----------------
__device__ __nv_bfloat16 g_ctx[(size_t)MTOK * D];   // 64MB shifted x, bf16
__device__ __nv_bfloat16 g_hb[(size_t)MTOK * D];    // 64MB gelu hidden, bf16
__device__ __nv_bfloat16 g_W1b[D * D];
__device__ __nv_bfloat16 g_W2b[D * D];
__device__ __nv_bfloat16 g_WcTb[D * D];
__device__ __nv_bfloat16 g_Wfb[D * D];              // bf16(W1 @ Wc)
__device__ float g_bf[D];                           // W1@bc + b1
__device__ float g_pooled[8 * D];
__device__ unsigned long long g_best[8];
__device__ float g_gate[8];
__device__ int   g_bestidx[8];
__device__ float g_bsnorm[8];
__device__ float g_sseP[8 * MTOK];                  // write-once partials per (colblk*2+wn, row)
__device__ float g_dtP[8 * MTOK];
__device__ float g_xnP[8 * MTOK];

// ---------------- helpers ----------------
__device__ __forceinline__ uint32_t smem_u32(const void* p){
    uint32_t a;
    asm("{ .reg .u64 t; cvta.to.shared.u64 t, %1; cvt.u32.u64 %0, t; }" : "=r"(a) : "l"(p));
    return a;
}
__device__ __forceinline__ uint32_t swz(uint32_t x){ return x ^ ((x >> 3) & 0x70); }
__device__ __forceinline__ void cp_async16(uint32_t dst, const void* src){
    asm volatile("cp.async.cg.shared.global [%0], [%1], 16;" :: "r"(dst), "l"(src) : "memory");
}
__device__ __forceinline__ void cp_commit(){
    asm volatile("cp.async.commit_group;" ::: "memory");
}
template<int N> __device__ __forceinline__ void cp_wait(){
    asm volatile("cp.async.wait_group %0;" :: "n"(N) : "memory");
}
__device__ __forceinline__ void ldsm_x4(uint32_t& r0, uint32_t& r1, uint32_t& r2, uint32_t& r3,
                                        uint32_t addr){
    asm volatile("ldmatrix.sync.aligned.m8n8.x4.shared.b16 {%0,%1,%2,%3}, [%4];"
                 : "=r"(r0), "=r"(r1), "=r"(r2), "=r"(r3) : "r"(addr));
}
__device__ __forceinline__ void mma16816(float* c, uint32_t a0, uint32_t a1, uint32_t a2,
                                         uint32_t a3, uint32_t b0, uint32_t b1){
    asm volatile("mma.sync.aligned.m16n8k16.row.col.f32.bf16.bf16.f32 "
                 "{%0,%1,%2,%3}, {%4,%5,%6,%7}, {%8,%9}, {%0,%1,%2,%3};"
                 : "+f"(c[0]), "+f"(c[1]), "+f"(c[2]), "+f"(c[3])
                 : "r"(a0), "r"(a1), "r"(a2), "r"(a3), "r"(b0), "r"(b1));
}
__device__ __forceinline__ float warp_sum(float v){
#pragma unroll
    for (int o = 16; o > 0; o >>= 1) v += __shfl_xor_sync(0xffffffffu, v, o);
    return v;
}
__device__ __forceinline__ float gelu_exact(float v){
    return 0.5f * v * (1.0f + erff(v * 0.70710678118654752f));
}
__device__ __forceinline__ uint32_t pack_bf2(float a, float b){
    __nv_bfloat162 h2 = __floats2bfloat162_rn(a, b);
    return *(uint32_t*)&h2;
}

// ---------------- small kernels ----------------
__global__ void init_kernel(){
    int t = threadIdx.x;  // 512
#pragma unroll
    for (int i = 0; i < 8; i++) g_pooled[t + i * 512] = 0.f;
    if (t < 8) g_best[t] = 0x007FFFFF00000000ull;
}

// W1/W2 -> bf16, fused bias bf[m] = W1[m]·bc + b1[m]
__global__ void convert_bias_kernel(const float* __restrict__ W1, const float* __restrict__ W2,
                                    const float* __restrict__ bc, const float* __restrict__ b1){
    __shared__ float red[16];
    int m = blockIdx.x, t = threadIdx.x;       // grid 512 x 512
    float v1 = W1[(size_t)m * D + t];
    g_W1b[(size_t)m * D + t] = __float2bfloat16(v1);
    g_W2b[(size_t)m * D + t] = __float2bfloat16(W2[(size_t)m * D + t]);
    float s = v1 * bc[t];
    s = warp_sum(s);
    if ((t & 31) == 0) red[t >> 5] = s;
    __syncthreads();
    if (t == 0){
        float a = 0.f;
#pragma unroll
        for (int w = 0; w < 16; w++) a += red[w];
        g_bf[m] = a + b1[m];
    }
}

__global__ void transpose_conv_kernel(const float* __restrict__ in){
    __shared__ float t[32][33];
    int bx = blockIdx.x * 32, by = blockIdx.y * 32;
    int txx = threadIdx.x, tyy = threadIdx.y;  // (32, 8)
#pragma unroll
    for (int i = 0; i < 32; i += 8)
        t[tyy + i][txx] = in[(size_t)(by + tyy + i) * D + bx + txx];
    __syncthreads();
#pragma unroll
    for (int i = 0; i < 32; i += 8)
        g_WcTb[(size_t)(bx + tyy + i) * D + by + txx] = __float2bfloat16(t[txx][tyy + i]);
}

// x -> ctx_bf16 (causal shift) + pooled sums; chunked by batch pair (b0 = batch base)
__global__ void conv_pool_kernel(const float* __restrict__ x, int b0){
    int b = b0 + blockIdx.x, seg = blockIdx.y;   // grid (2, 64)
    int d = threadIdx.x;                         // 256 threads; cols 2d, 2d+1
    if (seg == 0)
        *(uint32_t*)&g_ctx[(size_t)b * LSEQ * D + 2 * d] = 0u;   // ctx row 0 = 0
    const float2* xb = (const float2*)(x + ((size_t)b * LSEQ + (size_t)seg * 128) * D) + d;
    float s0 = 0.f, s1 = 0.f;
#pragma unroll 4
    for (int l = 0; l < 128; l++){
        float2 v = xb[(size_t)l * 256];
        s0 += v.x; s1 += v.y;
        int gl = seg * 128 + l;
        if (gl != LSEQ - 1)
            *(uint32_t*)&g_ctx[((size_t)b * LSEQ + gl + 1) * D + 2 * d] = pack_bf2(v.x, v.y);
    }
    atomicAdd(&g_pooled[b * D + 2 * d],     s0);
    atomicAdd(&g_pooled[b * D + 2 * d + 1], s1);
}

// ballot-driven cosine scan; pooled norms computed in-block
__global__ void sim_scan_kernel(const float* __restrict__ emb,
                                const float* __restrict__ act, int S){
    __shared__ float shp[8 * D];
    __shared__ float shn[8];
    __shared__ unsigned long long sbest[8][8];
    int tid = threadIdx.x;
    for (int i = tid; i < 8 * D; i += 256) shp[i] = g_pooled[i];
    __syncthreads();
    int warp = tid >> 5, lane = tid & 31;
    {   // warp w -> pooled norm of batch w
        float s = 0.f;
#pragma unroll
        for (int j = 0; j < 16; j++){ float v = shp[warp * D + lane + j * 32]; s = fmaf(v, v, s); }
        s = warp_sum(s);
        if (lane == 0) shn[warp] = fmaxf(sqrtf(s), 1e-8f);
    }
    __syncthreads();
    int s0 = (blockIdx.x * 8 + warp) * 32;   // grid 512 x 8 warps x 32 = 131072
    unsigned long long best[8];
#pragma unroll
    for (int b = 0; b < 8; b++) best[b] = 0x007FFFFF00000000ull;

    float av = (s0 + lane < S) ? act[s0 + lane] : 0.f;
    unsigned msk = __ballot_sync(0xffffffffu, av > 0.f);
    while (msk){
        int i = __ffs(msk) - 1; msk &= msk - 1;
        int s = s0 + i;
        const float* er = emb + (size_t)s * D;
        float acc[8] = {0,0,0,0,0,0,0,0};
        float nn = 0.f;
#pragma unroll
        for (int jj = 0; jj < 16; jj++){
            int d = lane + jj * 32;
            float e = er[d];
            nn = fmaf(e, e, nn);
#pragma unroll
            for (int b = 0; b < 8; b++) acc[b] = fmaf(e, shp[b * D + d], acc[b]);
        }
        nn = warp_sum(nn);
#pragma unroll
        for (int b = 0; b < 8; b++) acc[b] = warp_sum(acc[b]);
        if (lane == 0){
            float ne = fmaxf(sqrtf(nn), 1e-8f);
#pragma unroll
            for (int b = 0; b < 8; b++){
                float sim = acc[b] / (shn[b] * ne);
                unsigned u = __float_as_uint(sim);
                unsigned en = (u & 0x80000000u) ? ~u : (u | 0x80000000u);
                unsigned long long p = ((unsigned long long)en << 32)
                                     | (unsigned)(0xFFFFFFFFu - (unsigned)s);
                if (p > best[b]) best[b] = p;
            }
        }
    }
    if (lane == 0){
#pragma unroll
        for (int b = 0; b < 8; b++) sbest[warp][b] = best[b];
    }
    __syncthreads();
    if (tid < 8){
        unsigned long long m = sbest[0][tid];
#pragma unroll
        for (int w = 1; w < 8; w++) if (sbest[w][tid] > m) m = sbest[w][tid];
        atomicMax(&g_best[tid], m);
    }
}

__global__ void decode_kernel(const float* __restrict__ emb){
    __shared__ int sidx[8];
    int tid = threadIdx.x;  // 256
    if (tid < 8){
        unsigned long long p = g_best[tid];
        unsigned en = (unsigned)(p >> 32);
        unsigned u = (en & 0x80000000u) ? (en & 0x7FFFFFFFu) : ~en;
        float ms = __uint_as_float(u);
        int idx = (int)(0xFFFFFFFFu - (unsigned)p);
        if (!(ms > -INFINITY)) idx = 0;
        sidx[tid] = idx;
        g_bestidx[tid] = idx;
        g_gate[tid] = (ms > 0.3f) ? 2.0f : 0.0f;
    }
    __syncthreads();
    int warp = tid >> 5, lane = tid & 31;
    const float* er = emb + (size_t)sidx[warp] * D;
    float s = 0.f;
    for (int j = lane; j < D; j += 32){ float v = er[j]; s += v * v; }
    s = warp_sum(s);
    if (lane == 0) g_bsnorm[warp] = fmaxf(sqrtf(s), 1e-8f);
}

// ---------------- HMMA NT GEMM: C[m][n] = sum_k A[m][k]*B[n][k] ---------------
// MODE 0: plain->bf16   MODE 1: gelu(.+bias)->bf16
template<int MODE>
__global__ void __launch_bounds__(256, 2) mma_gemm_nt(
    const __nv_bfloat16* __restrict__ A, const __nv_bfloat16* __restrict__ B,
    const float* __restrict__ bias, __nv_bfloat16* __restrict__ C)
{
    extern __shared__ __align__(1024) char smem[];
    __shared__ float sbias[128];
    const int tid = threadIdx.x;
    const int wid = tid >> 5, lane = tid & 31;
    const int row0 = blockIdx.y * 128, col0 = blockIdx.x * 128;
    const int wm = wid & 3, wn = wid >> 2;
    uint32_t sb = smem_u32(smem);
    uint32_t sA = sb;            // [2][16KB]
    uint32_t sB = sb + 32768;    // [2][16KB]

    auto load_chunk = [&](int st, int c){
        int k0 = c * 64;
#pragma unroll
        for (int i = 0; i < 4; i++){
            int lin = tid + i * 256;
            int r = lin >> 3, sg = lin & 7;
            cp_async16(sA + st * 16384 + swz(r * 128 + sg * 16),
                       A + (size_t)(row0 + r) * D + k0 + sg * 8);
        }
#pragma unroll
        for (int i = 0; i < 4; i++){
            int lin = tid + i * 256;
            int r = lin >> 3, sg = lin & 7;
            cp_async16(sB + st * 16384 + swz(r * 128 + sg * 16),
                       B + (size_t)(col0 + r) * D + k0 + sg * 8);
        }
        cp_commit();
    };

    load_chunk(0, 0);
    load_chunk(1, 1);

    float acc[2][8][4];
#pragma unroll
    for (int mt = 0; mt < 2; mt++)
#pragma unroll
        for (int nt = 0; nt < 8; nt++)
#pragma unroll
            for (int q = 0; q < 4; q++) acc[mt][nt][q] = 0.f;

    for (int c = 0; c < 8; c++){
        int st = c & 1;
        if (c < 7) cp_wait<1>(); else cp_wait<0>();
        __syncthreads();
        uint32_t a_base = sA + st * 16384;
        uint32_t b_base = sB + st * 16384;
#pragma unroll
        for (int ks = 0; ks < 4; ks++){
            int kb = ks * 16;
            uint32_t af[2][4];
#pragma unroll
            for (int mt = 0; mt < 2; mt++){
                int r  = wm * 32 + mt * 16 + (lane & 15);
                int kk = kb + ((lane >> 4) << 3);
                ldsm_x4(af[mt][0], af[mt][1], af[mt][2], af[mt][3],
                        a_base + swz(r * 128 + kk * 2));
            }
            uint32_t bf[8][2];
#pragma unroll
            for (int np = 0; np < 4; np++){
                int nr = wn * 64 + np * 16 + (lane & 7) + ((lane >> 4) << 3);
                int kk = kb + (((lane >> 3) & 1) << 3);
                uint32_t t0, t1, t2, t3;
                ldsm_x4(t0, t1, t2, t3, b_base + swz(nr * 128 + kk * 2));
                bf[np * 2][0] = t0;     bf[np * 2][1] = t1;
                bf[np * 2 + 1][0] = t2; bf[np * 2 + 1][1] = t3;
            }
#pragma unroll
            for (int mt = 0; mt < 2; mt++)
#pragma unroll
                for (int nt = 0; nt < 8; nt++)
                    mma16816(acc[mt][nt], af[mt][0], af[mt][1], af[mt][2], af[mt][3],
                             bf[nt][0], bf[nt][1]);
        }
        __syncthreads();
        if (c + 2 < 8) load_chunk(st, c + 2);
    }

    if (MODE >= 1){
        if (tid < 128) sbias[tid] = bias[col0 + tid];
        __syncthreads();
    }

#pragma unroll
    for (int mt = 0; mt < 2; mt++){
        int gm0 = row0 + wm * 32 + mt * 16 + (lane >> 2);
#pragma unroll
        for (int nt = 0; nt < 8; nt++){
            int ln = wn * 64 + nt * 8 + (lane & 3) * 2;
            int gn = col0 + ln;
            float v0 = acc[mt][nt][0], v1 = acc[mt][nt][1];
            float v2 = acc[mt][nt][2], v3 = acc[mt][nt][3];
            if (MODE >= 1){
                float b0v = sbias[ln], b1v = sbias[ln + 1];
                v0 += b0v; v1 += b1v; v2 += b0v; v3 += b1v;
            }
            if (MODE == 1){
                v0 = gelu_exact(v0); v1 = gelu_exact(v1);
                v2 = gelu_exact(v2); v3 = gelu_exact(v3);
            }
            *(uint32_t*)(C + (size_t)gm0 * D + gn)       = pack_bf2(v0, v1);
            *(uint32_t*)(C + (size_t)(gm0 + 8) * D + gn) = pack_bf2(v2, v3);
        }
    }
}

// ---------------- GEMM2 fused: pred = h@W2^T+b2 consumed in-register ----------
// epilogue: write-once per-(colblk, n-half) row partials — no atomics, no pre-zero
__global__ void __launch_bounds__(256, 2) mma_gemm2_fused(
    const __nv_bfloat16* __restrict__ A, const __nv_bfloat16* __restrict__ B,
    const float* __restrict__ b2, const float* __restrict__ x,
    const float* __restrict__ emb)
{
    extern __shared__ __align__(1024) char smem[];
    __shared__ float sbias[128];
    __shared__ float semb[128];
    const int tid = threadIdx.x;
    const int wid = tid >> 5, lane = tid & 31;
    const int row0 = blockIdx.y * 128, col0 = blockIdx.x * 128;
    const int wm = wid & 3, wn = wid >> 2;
    uint32_t sb = smem_u32(smem);
    uint32_t sA = sb;
    uint32_t sB = sb + 32768;

    auto load_chunk = [&](int st, int c){
        int k0 = c * 64;
#pragma unroll
        for (int i = 0; i < 4; i++){
            int lin = tid + i * 256;
            int r = lin >> 3, sg = lin & 7;
            cp_async16(sA + st * 16384 + swz(r * 128 + sg * 16),
                       A + (size_t)(row0 + r) * D + k0 + sg * 8);
        }
#pragma unroll
        for (int i = 0; i < 4; i++){
            int lin = tid + i * 256;
            int r = lin >> 3, sg = lin & 7;
            cp_async16(sB + st * 16384 + swz(r * 128 + sg * 16),
                       B + (size_t)(col0 + r) * D + k0 + sg * 8);
        }
        cp_commit();
    };

    load_chunk(0, 0);
    load_chunk(1, 1);

    float acc[2][8][4];
#pragma unroll
    for (int mt = 0; mt < 2; mt++)
#pragma unroll
        for (int nt = 0; nt < 8; nt++)
#pragma unroll
            for (int q = 0; q < 4; q++) acc[mt][nt][q] = 0.f;

    for (int c = 0; c < 8; c++){
        int st = c & 1;
        if (c < 7) cp_wait<1>(); else cp_wait<0>();
        __syncthreads();
        uint32_t a_base = sA + st * 16384;
        uint32_t b_base = sB + st * 16384;
#pragma unroll
        for (int ks = 0; ks < 4; ks++){
            int kb = ks * 16;
            uint32_t af[2][4];
#pragma unroll
            for (int mt = 0; mt < 2; mt++){
                int r  = wm * 32 + mt * 16 + (lane & 15);
                int kk = kb + ((lane >> 4) << 3);
                ldsm_x4(af[mt][0], af[mt][1], af[mt][2], af[mt][3],
                        a_base + swz(r * 128 + kk * 2));
            }
            uint32_t bf[8][2];
#pragma unroll
            for (int np = 0; np < 4; np++){
                int nr = wn * 64 + np * 16 + (lane & 7) + ((lane >> 4) << 3);
                int kk = kb + (((lane >> 3) & 1) << 3);
                uint32_t t0, t1, t2, t3;
                ldsm_x4(t0, t1, t2, t3, b_base + swz(nr * 128 + kk * 2));
                bf[np * 2][0] = t0;     bf[np * 2][1] = t1;
                bf[np * 2 + 1][0] = t2; bf[np * 2 + 1][1] = t3;
            }
#pragma unroll
            for (int mt = 0; mt < 2; mt++)
#pragma unroll
                for (int nt = 0; nt < 8; nt++)
                    mma16816(acc[mt][nt], af[mt][0], af[mt][1], af[mt][2], af[mt][3],
                             bf[nt][0], bf[nt][1]);
        }
        __syncthreads();
        if (c + 2 < 8) load_chunk(st, c + 2);
    }

    int bi = g_bestidx[row0 >> 13];
    if (tid < 128) sbias[tid] = b2[col0 + tid];
    else if (tid < 256) semb[tid - 128] = emb[(size_t)bi * D + col0 + tid - 128];
    __syncthreads();

    const int part = (blockIdx.x * 2 + wn) * MTOK;   // unique per (colblk, n-half)
#pragma unroll
    for (int mt = 0; mt < 2; mt++){
#pragma unroll
        for (int h2 = 0; h2 < 2; h2++){
            int gm = row0 + wm * 32 + mt * 16 + (lane >> 2) + h2 * 8;
            float ls = 0.f, ld = 0.f, lx = 0.f;
#pragma unroll
            for (int nt = 0; nt < 8; nt++){
                int ln = wn * 64 + nt * 8 + (lane & 3) * 2;
                float2 xv = *(const float2*)(x + (size_t)gm * D + col0 + ln);
                float p0 = acc[mt][nt][h2 * 2 + 0] + sbias[ln];
                float p1 = acc[mt][nt][h2 * 2 + 1] + sbias[ln + 1];
                float d0 = xv.x - p0, d1 = xv.y - p1;
                ls = fmaf(d0, d0, fmaf(d1, d1, ls));
                ld = fmaf(xv.x, semb[ln], fmaf(xv.y, semb[ln + 1], ld));
                lx = fmaf(xv.x, xv.x, fmaf(xv.y, xv.y, lx));
            }
            ls += __shfl_xor_sync(0xffffffffu, ls, 1);
            ls += __shfl_xor_sync(0xffffffffu, ls, 2);
            ld += __shfl_xor_sync(0xffffffffu, ld, 1);
            ld += __shfl_xor_sync(0xffffffffu, ld, 2);
            lx += __shfl_xor_sync(0xffffffffu, lx, 1);
            lx += __shfl_xor_sync(0xffffffffu, lx, 2);
            if ((lane & 3) == 0){
                g_sseP[part + gm] = ls;
                g_dtP[part + gm]  = ld;
                g_xnP[part + gm]  = lx;
            }
        }
    }
}

// ---------------- final: combine 8 partials per row -> surprise --------------
__global__ void surprise_final_kernel(float* __restrict__ out){
    int row = blockIdx.x * 256 + threadIdx.x;  // grid 256
    int b = row >> 13;
    float sse = 0.f, dt = 0.f, xn = 0.f;
#pragma unroll
    for (int p = 0; p < 8; p++){
        sse += g_sseP[p * MTOK + row];
        dt  += g_dtP[p * MTOK + row];
        xn  += g_xnP[p * MTOK + row];
    }
    float ps = sqrtf(sse * (1.0f / 512.0f));
    float na = fmaxf(sqrtf(xn), 1e-8f);
    float dv = 1.0f - dt / (na * g_bsnorm[b]);
    out[row] = fmaxf(ps, g_gate[b] * dv);
}

// ---------------- launch (chunk-pipelined conv_pool || gemm1) ----------------
extern "C" void kernel_launch(void* const* d_in, const int* in_sizes, int n_in,
                              void* d_out, int out_size){
    const float* x  = (const float*)d_in[0];
    const float* Wc = (const float*)d_in[1];
    const float* bc = (const float*)d_in[2];
    const float* W1 = (const float*)d_in[3];
    const float* b1 = (const float*)d_in[4];
    const float* W2 = (const float*)d_in[5];
    const float* b2 = (const float*)d_in[6];
    const float* emb= (const float*)d_in[7];
    const float* act= (const float*)d_in[8];
    float* out = (float*)d_out;
    const int S = in_sizes[8];        // 131072
    const int M = in_sizes[0] / D;    // 65536 tokens

    __nv_bfloat16 *pCtx, *pHb, *pW1b, *pWcTb, *pWfb, *pW2b;
    float* pbf;
    cudaGetSymbolAddress((void**)&pCtx,  g_ctx);
    cudaGetSymbolAddress((void**)&pHb,   g_hb);
    cudaGetSymbolAddress((void**)&pW1b,  g_W1b);
    cudaGetSymbolAddress((void**)&pWcTb, g_WcTb);
    cudaGetSymbolAddress((void**)&pWfb,  g_Wfb);
    cudaGetSymbolAddress((void**)&pW2b,  g_W2b);
    cudaGetSymbolAddress((void**)&pbf,   g_bf);

    const int GSMEM = 65536;  // 2 stages x (16KB A + 16KB B)
    const int NCH = M / CHUNK;        // 4
    static bool once = false;
    static cudaStream_t sW = nullptr, sS = nullptr, sG = nullptr;
    static cudaEvent_t evStart = nullptr, evW = nullptr, evS = nullptr, evG1 = nullptr;
    static cudaEvent_t evC[8];
    if (!once){
        cudaFuncSetAttribute(mma_gemm_nt<0>, cudaFuncAttributeMaxDynamicSharedMemorySize, GSMEM);
        cudaFuncSetAttribute(mma_gemm_nt<1>, cudaFuncAttributeMaxDynamicSharedMemorySize, GSMEM);
        cudaFuncSetAttribute(mma_gemm2_fused, cudaFuncAttributeMaxDynamicSharedMemorySize, GSMEM);
        cudaStreamCreateWithFlags(&sW, cudaStreamNonBlocking);
        cudaStreamCreateWithFlags(&sS, cudaStreamNonBlocking);
        cudaStreamCreateWithFlags(&sG, cudaStreamNonBlocking);
        cudaEventCreateWithFlags(&evStart, cudaEventDisableTiming);
        cudaEventCreateWithFlags(&evW,     cudaEventDisableTiming);
        cudaEventCreateWithFlags(&evS,     cudaEventDisableTiming);
        cudaEventCreateWithFlags(&evG1,    cudaEventDisableTiming);
        for (int c = 0; c < 8; c++) cudaEventCreateWithFlags(&evC[c], cudaEventDisableTiming);
        once = true;
    }

    init_kernel<<<1, 512>>>();
    cudaEventRecord(evStart, 0);

    // weight chain on sW: convert + transpose + Wf GEMM
    cudaStreamWaitEvent(sW, evStart, 0);
    convert_bias_kernel<<<512, 512, 0, sW>>>(W1, W2, bc, b1);
    transpose_conv_kernel<<<dim3(16, 16), dim3(32, 8), 0, sW>>>(Wc);
    mma_gemm_nt<0><<<dim3(4, 4), 256, GSMEM, sW>>>(pW1b, pWcTb, nullptr, pWfb); // Wf = W1@Wc
    cudaEventRecord(evW, sW);

    // main: chunked x -> ctx + pooled (sequential; event per chunk)
    for (int c = 0; c < NCH; c++){
        conv_pool_kernel<<<dim3(2, 64), 256>>>(x, c * 2);
        cudaEventRecord(evC[c], 0);
    }

    // gemm1 sub-launches on sG: chunk c waits weights + conv chunk c
    cudaStreamWaitEvent(sG, evW, 0);
    for (int c = 0; c < NCH; c++){
        cudaStreamWaitEvent(sG, evC[c], 0);
        mma_gemm_nt<1><<<dim3(4, CHUNK / 128), 256, GSMEM, sG>>>(
            pCtx + (size_t)c * CHUNK * D, pWfb, pbf, pHb + (size_t)c * CHUNK * D);
    }
    cudaEventRecord(evG1, sG);

    // scan chain on sS after pooled complete (overlaps gemm1 tail)
    cudaStreamWaitEvent(sS, evC[NCH - 1], 0);
    sim_scan_kernel<<<512, 256, 0, sS>>>(emb, act, S);
    decode_kernel<<<1, 256, 0, sS>>>(emb);
    cudaEventRecord(evS, sS);

    // gemm2 on main stream needs gemm1 + decode
    cudaStreamWaitEvent(0, evG1, 0);
    cudaStreamWaitEvent(0, evS, 0);
    mma_gemm2_fused<<<dim3(4, M / 128), 256, GSMEM>>>(pHb, pW2b, b2, x, emb);   // surprise partials
    surprise_final_kernel<<<M / 256, 256>>>(out);
}

// round 15
// speedup vs baseline: 1.0618x; 1.0618x over previous
#include <cuda_runtime.h>
#include <cuda_bf16.h>
#include <cstdint>
#include <cstddef>
#include <math.h>

#define D 512
#define LSEQ 8192
#define MTOK 65536

// ---------------- scratch (static __device__, no allocs) ----------------
__device__ __nv_bfloat16 g_ctx[(size_t)MTOK * D];   // 64MB shifted x, bf16
__device__ __nv_bfloat16 g_hb[(size_t)MTOK * D];    // 64MB gelu hidden, bf16
__device__ __nv_bfloat16 g_W1b[D * D];
__device__ __nv_bfloat16 g_W2b[D * D];
__device__ __nv_bfloat16 g_WcTb[D * D];
__device__ __nv_bfloat16 g_Wfb[D * D];              // bf16(W1 @ Wc)
__device__ float g_bf[D];                           // W1@bc + b1
__device__ float g_pooled[8 * D];
__device__ unsigned long long g_best[8];
__device__ float g_gate[8];
__device__ int   g_bestidx[8];
__device__ float g_bsnorm[8];
__device__ float g_sseP[8 * MTOK];                  // write-once partials per (colblk*2+wn, row)
__device__ float g_dtP[8 * MTOK];
__device__ float g_xnP[8 * MTOK];

// ---------------- helpers ----------------
__device__ __forceinline__ uint32_t smem_u32(const void* p){
    uint32_t a;
    asm("{ .reg .u64 t; cvta.to.shared.u64 t, %1; cvt.u32.u64 %0, t; }" : "=r"(a) : "l"(p));
    return a;
}
__device__ __forceinline__ uint32_t swz(uint32_t x){ return x ^ ((x >> 3) & 0x70); }
__device__ __forceinline__ void cp_async16(uint32_t dst, const void* src){
    asm volatile("cp.async.cg.shared.global [%0], [%1], 16;" :: "r"(dst), "l"(src) : "memory");
}
__device__ __forceinline__ void cp_commit(){
    asm volatile("cp.async.commit_group;" ::: "memory");
}
template<int N> __device__ __forceinline__ void cp_wait(){
    asm volatile("cp.async.wait_group %0;" :: "n"(N) : "memory");
}
__device__ __forceinline__ void ldsm_x4(uint32_t& r0, uint32_t& r1, uint32_t& r2, uint32_t& r3,
                                        uint32_t addr){
    asm volatile("ldmatrix.sync.aligned.m8n8.x4.shared.b16 {%0,%1,%2,%3}, [%4];"
                 : "=r"(r0), "=r"(r1), "=r"(r2), "=r"(r3) : "r"(addr));
}
__device__ __forceinline__ void mma16816(float* c, uint32_t a0, uint32_t a1, uint32_t a2,
                                         uint32_t a3, uint32_t b0, uint32_t b1){
    asm volatile("mma.sync.aligned.m16n8k16.row.col.f32.bf16.bf16.f32 "
                 "{%0,%1,%2,%3}, {%4,%5,%6,%7}, {%8,%9}, {%0,%1,%2,%3};"
                 : "+f"(c[0]), "+f"(c[1]), "+f"(c[2]), "+f"(c[3])
                 : "r"(a0), "r"(a1), "r"(a2), "r"(a3), "r"(b0), "r"(b1));
}
__device__ __forceinline__ float warp_sum(float v){
#pragma unroll
    for (int o = 16; o > 0; o >>= 1) v += __shfl_xor_sync(0xffffffffu, v, o);
    return v;
}
__device__ __forceinline__ float gelu_exact(float v){
    return 0.5f * v * (1.0f + erff(v * 0.70710678118654752f));
}
__device__ __forceinline__ uint32_t pack_bf2(float a, float b){
    __nv_bfloat162 h2 = __floats2bfloat162_rn(a, b);
    return *(uint32_t*)&h2;
}

// ---------------- small kernels ----------------
__global__ void init_kernel(){
    int t = threadIdx.x;  // 512
#pragma unroll
    for (int i = 0; i < 8; i++) g_pooled[t + i * 512] = 0.f;
    if (t < 8) g_best[t] = 0x007FFFFF00000000ull;
}

// W1/W2 -> bf16, fused bias bf[m] = W1[m]·bc + b1[m]
__global__ void convert_bias_kernel(const float* __restrict__ W1, const float* __restrict__ W2,
                                    const float* __restrict__ bc, const float* __restrict__ b1){
    __shared__ float red[16];
    int m = blockIdx.x, t = threadIdx.x;       // grid 512 x 512
    float v1 = W1[(size_t)m * D + t];
    g_W1b[(size_t)m * D + t] = __float2bfloat16(v1);
    g_W2b[(size_t)m * D + t] = __float2bfloat16(W2[(size_t)m * D + t]);
    float s = v1 * bc[t];
    s = warp_sum(s);
    if ((t & 31) == 0) red[t >> 5] = s;
    __syncthreads();
    if (t == 0){
        float a = 0.f;
#pragma unroll
        for (int w = 0; w < 16; w++) a += red[w];
        g_bf[m] = a + b1[m];
    }
}

__global__ void transpose_conv_kernel(const float* __restrict__ in){
    __shared__ float t[32][33];
    int bx = blockIdx.x * 32, by = blockIdx.y * 32;
    int txx = threadIdx.x, tyy = threadIdx.y;  // (32, 8)
#pragma unroll
    for (int i = 0; i < 32; i += 8)
        t[tyy + i][txx] = in[(size_t)(by + tyy + i) * D + bx + txx];
    __syncthreads();
#pragma unroll
    for (int i = 0; i < 32; i += 8)
        g_WcTb[(size_t)(bx + tyy + i) * D + by + txx] = __float2bfloat16(t[txx][tyy + i]);
}

// x -> ctx_bf16 (causal shift) + pooled sums; float4 loads, uint2 (4xbf16) stores
__global__ void conv_pool_kernel(const float* __restrict__ x){
    int b = blockIdx.x, seg = blockIdx.y;   // grid (8, 64)
    int t = threadIdx.x;                    // 128 threads; cols 4t..4t+3
    if (seg == 0){
        uint2 z; z.x = 0u; z.y = 0u;
        *(uint2*)&g_ctx[(size_t)b * LSEQ * D + 4 * t] = z;   // ctx row 0 = 0
    }
    const float4* xb = (const float4*)(x + ((size_t)b * LSEQ + (size_t)seg * 128) * D) + t;
    float s0 = 0.f, s1 = 0.f, s2 = 0.f, s3 = 0.f;
#pragma unroll 4
    for (int l = 0; l < 128; l++){
        float4 v = xb[(size_t)l * 128];
        s0 += v.x; s1 += v.y; s2 += v.z; s3 += v.w;
        int gl = seg * 128 + l;
        if (gl != LSEQ - 1){
            uint2 w;
            w.x = pack_bf2(v.x, v.y);
            w.y = pack_bf2(v.z, v.w);
            *(uint2*)&g_ctx[((size_t)b * LSEQ + gl + 1) * D + 4 * t] = w;
        }
    }
    atomicAdd(&g_pooled[b * D + 4 * t],     s0);
    atomicAdd(&g_pooled[b * D + 4 * t + 1], s1);
    atomicAdd(&g_pooled[b * D + 4 * t + 2], s2);
    atomicAdd(&g_pooled[b * D + 4 * t + 3], s3);
}

// ballot-driven cosine scan; pooled norms computed in-block
__global__ void sim_scan_kernel(const float* __restrict__ emb,
                                const float* __restrict__ act, int S){
    __shared__ float shp[8 * D];
    __shared__ float shn[8];
    __shared__ unsigned long long sbest[8][8];
    int tid = threadIdx.x;
    for (int i = tid; i < 8 * D; i += 256) shp[i] = g_pooled[i];
    __syncthreads();
    int warp = tid >> 5, lane = tid & 31;
    {   // warp w -> pooled norm of batch w
        float s = 0.f;
#pragma unroll
        for (int j = 0; j < 16; j++){ float v = shp[warp * D + lane + j * 32]; s = fmaf(v, v, s); }
        s = warp_sum(s);
        if (lane == 0) shn[warp] = fmaxf(sqrtf(s), 1e-8f);
    }
    __syncthreads();
    int s0 = (blockIdx.x * 8 + warp) * 32;   // grid 512 x 8 warps x 32 = 131072
    unsigned long long best[8];
#pragma unroll
    for (int b = 0; b < 8; b++) best[b] = 0x007FFFFF00000000ull;

    float av = (s0 + lane < S) ? act[s0 + lane] : 0.f;
    unsigned msk = __ballot_sync(0xffffffffu, av > 0.f);
    while (msk){
        int i = __ffs(msk) - 1; msk &= msk - 1;
        int s = s0 + i;
        const float* er = emb + (size_t)s * D;
        float acc[8] = {0,0,0,0,0,0,0,0};
        float nn = 0.f;
#pragma unroll
        for (int jj = 0; jj < 16; jj++){
            int d = lane + jj * 32;
            float e = er[d];
            nn = fmaf(e, e, nn);
#pragma unroll
            for (int b = 0; b < 8; b++) acc[b] = fmaf(e, shp[b * D + d], acc[b]);
        }
        nn = warp_sum(nn);
#pragma unroll
        for (int b = 0; b < 8; b++) acc[b] = warp_sum(acc[b]);
        if (lane == 0){
            float ne = fmaxf(sqrtf(nn), 1e-8f);
#pragma unroll
            for (int b = 0; b < 8; b++){
                float sim = acc[b] / (shn[b] * ne);
                unsigned u = __float_as_uint(sim);
                unsigned en = (u & 0x80000000u) ? ~u : (u | 0x80000000u);
                unsigned long long p = ((unsigned long long)en << 32)
                                     | (unsigned)(0xFFFFFFFFu - (unsigned)s);
                if (p > best[b]) best[b] = p;
            }
        }
    }
    if (lane == 0){
#pragma unroll
        for (int b = 0; b < 8; b++) sbest[warp][b] = best[b];
    }
    __syncthreads();
    if (tid < 8){
        unsigned long long m = sbest[0][tid];
#pragma unroll
        for (int w = 1; w < 8; w++) if (sbest[w][tid] > m) m = sbest[w][tid];
        atomicMax(&g_best[tid], m);
    }
}

__global__ void decode_kernel(const float* __restrict__ emb){
    __shared__ int sidx[8];
    int tid = threadIdx.x;  // 256
    if (tid < 8){
        unsigned long long p = g_best[tid];
        unsigned en = (unsigned)(p >> 32);
        unsigned u = (en & 0x80000000u) ? (en & 0x7FFFFFFFu) : ~en;
        float ms = __uint_as_float(u);
        int idx = (int)(0xFFFFFFFFu - (unsigned)p);
        if (!(ms > -INFINITY)) idx = 0;
        sidx[tid] = idx;
        g_bestidx[tid] = idx;
        g_gate[tid] = (ms > 0.3f) ? 2.0f : 0.0f;
    }
    __syncthreads();
    int warp = tid >> 5, lane = tid & 31;
    const float* er = emb + (size_t)sidx[warp] * D;
    float s = 0.f;
    for (int j = lane; j < D; j += 32){ float v = er[j]; s += v * v; }
    s = warp_sum(s);
    if (lane == 0) g_bsnorm[warp] = fmaxf(sqrtf(s), 1e-8f);
}

// ---------------- HMMA NT GEMM: C[m][n] = sum_k A[m][k]*B[n][k] ---------------
// MODE 0: plain->bf16   MODE 1: gelu(.+bias)->bf16
template<int MODE>
__global__ void __launch_bounds__(256, 2) mma_gemm_nt(
    const __nv_bfloat16* __restrict__ A, const __nv_bfloat16* __restrict__ B,
    const float* __restrict__ bias, __nv_bfloat16* __restrict__ C)
{
    extern __shared__ __align__(1024) char smem[];
    __shared__ float sbias[128];
    const int tid = threadIdx.x;
    const int wid = tid >> 5, lane = tid & 31;
    const int row0 = blockIdx.y * 128, col0 = blockIdx.x * 128;
    const int wm = wid & 3, wn = wid >> 2;
    uint32_t sb = smem_u32(smem);
    uint32_t sA = sb;            // [2][16KB]
    uint32_t sB = sb + 32768;    // [2][16KB]

    auto load_chunk = [&](int st, int c){
        int k0 = c * 64;
#pragma unroll
        for (int i = 0; i < 4; i++){
            int lin = tid + i * 256;
            int r = lin >> 3, sg = lin & 7;
            cp_async16(sA + st * 16384 + swz(r * 128 + sg * 16),
                       A + (size_t)(row0 + r) * D + k0 + sg * 8);
        }
#pragma unroll
        for (int i = 0; i < 4; i++){
            int lin = tid + i * 256;
            int r = lin >> 3, sg = lin & 7;
            cp_async16(sB + st * 16384 + swz(r * 128 + sg * 16),
                       B + (size_t)(col0 + r) * D + k0 + sg * 8);
        }
        cp_commit();
    };

    load_chunk(0, 0);
    load_chunk(1, 1);

    float acc[2][8][4];
#pragma unroll
    for (int mt = 0; mt < 2; mt++)
#pragma unroll
        for (int nt = 0; nt < 8; nt++)
#pragma unroll
            for (int q = 0; q < 4; q++) acc[mt][nt][q] = 0.f;

    for (int c = 0; c < 8; c++){
        int st = c & 1;
        if (c < 7) cp_wait<1>(); else cp_wait<0>();
        __syncthreads();
        uint32_t a_base = sA + st * 16384;
        uint32_t b_base = sB + st * 16384;
#pragma unroll
        for (int ks = 0; ks < 4; ks++){
            int kb = ks * 16;
            uint32_t af[2][4];
#pragma unroll
            for (int mt = 0; mt < 2; mt++){
                int r  = wm * 32 + mt * 16 + (lane & 15);
                int kk = kb + ((lane >> 4) << 3);
                ldsm_x4(af[mt][0], af[mt][1], af[mt][2], af[mt][3],
                        a_base + swz(r * 128 + kk * 2));
            }
            uint32_t bf[8][2];
#pragma unroll
            for (int np = 0; np < 4; np++){
                int nr = wn * 64 + np * 16 + (lane & 7) + ((lane >> 4) << 3);
                int kk = kb + (((lane >> 3) & 1) << 3);
                uint32_t t0, t1, t2, t3;
                ldsm_x4(t0, t1, t2, t3, b_base + swz(nr * 128 + kk * 2));
                bf[np * 2][0] = t0;     bf[np * 2][1] = t1;
                bf[np * 2 + 1][0] = t2; bf[np * 2 + 1][1] = t3;
            }
#pragma unroll
            for (int mt = 0; mt < 2; mt++)
#pragma unroll
                for (int nt = 0; nt < 8; nt++)
                    mma16816(acc[mt][nt], af[mt][0], af[mt][1], af[mt][2], af[mt][3],
                             bf[nt][0], bf[nt][1]);
        }
        __syncthreads();
        if (c + 2 < 8) load_chunk(st, c + 2);
    }

    if (MODE >= 1){
        if (tid < 128) sbias[tid] = bias[col0 + tid];
        __syncthreads();
    }

#pragma unroll
    for (int mt = 0; mt < 2; mt++){
        int gm0 = row0 + wm * 32 + mt * 16 + (lane >> 2);
#pragma unroll
        for (int nt = 0; nt < 8; nt++){
            int ln = wn * 64 + nt * 8 + (lane & 3) * 2;
            int gn = col0 + ln;
            float v0 = acc[mt][nt][0], v1 = acc[mt][nt][1];
            float v2 = acc[mt][nt][2], v3 = acc[mt][nt][3];
            if (MODE >= 1){
                float b0v = sbias[ln], b1v = sbias[ln + 1];
                v0 += b0v; v1 += b1v; v2 += b0v; v3 += b1v;
            }
            if (MODE == 1){
                v0 = gelu_exact(v0); v1 = gelu_exact(v1);
                v2 = gelu_exact(v2); v3 = gelu_exact(v3);
            }
            *(uint32_t*)(C + (size_t)gm0 * D + gn)       = pack_bf2(v0, v1);
            *(uint32_t*)(C + (size_t)(gm0 + 8) * D + gn) = pack_bf2(v2, v3);
        }
    }
}

// ---------------- GEMM2 fused: pred = h@W2^T+b2 consumed in-register ----------
// epilogue: write-once per-(colblk, n-half) row partials — no atomics, no pre-zero
__global__ void __launch_bounds__(256, 2) mma_gemm2_fused(
    const __nv_bfloat16* __restrict__ A, const __nv_bfloat16* __restrict__ B,
    const float* __restrict__ b2, const float* __restrict__ x,
    const float* __restrict__ emb)
{
    extern __shared__ __align__(1024) char smem[];
    __shared__ float sbias[128];
    __shared__ float semb[128];
    const int tid = threadIdx.x;
    const int wid = tid >> 5, lane = tid & 31;
    const int row0 = blockIdx.y * 128, col0 = blockIdx.x * 128;
    const int wm = wid & 3, wn = wid >> 2;
    uint32_t sb = smem_u32(smem);
    uint32_t sA = sb;
    uint32_t sB = sb + 32768;

    auto load_chunk = [&](int st, int c){
        int k0 = c * 64;
#pragma unroll
        for (int i = 0; i < 4; i++){
            int lin = tid + i * 256;
            int r = lin >> 3, sg = lin & 7;
            cp_async16(sA + st * 16384 + swz(r * 128 + sg * 16),
                       A + (size_t)(row0 + r) * D + k0 + sg * 8);
        }
#pragma unroll
        for (int i = 0; i < 4; i++){
            int lin = tid + i * 256;
            int r = lin >> 3, sg = lin & 7;
            cp_async16(sB + st * 16384 + swz(r * 128 + sg * 16),
                       B + (size_t)(col0 + r) * D + k0 + sg * 8);
        }
        cp_commit();
    };

    load_chunk(0, 0);
    load_chunk(1, 1);

    float acc[2][8][4];
#pragma unroll
    for (int mt = 0; mt < 2; mt++)
#pragma unroll
        for (int nt = 0; nt < 8; nt++)
#pragma unroll
            for (int q = 0; q < 4; q++) acc[mt][nt][q] = 0.f;

    for (int c = 0; c < 8; c++){
        int st = c & 1;
        if (c < 7) cp_wait<1>(); else cp_wait<0>();
        __syncthreads();
        uint32_t a_base = sA + st * 16384;
        uint32_t b_base = sB + st * 16384;
#pragma unroll
        for (int ks = 0; ks < 4; ks++){
            int kb = ks * 16;
            uint32_t af[2][4];
#pragma unroll
            for (int mt = 0; mt < 2; mt++){
                int r  = wm * 32 + mt * 16 + (lane & 15);
                int kk = kb + ((lane >> 4) << 3);
                ldsm_x4(af[mt][0], af[mt][1], af[mt][2], af[mt][3],
                        a_base + swz(r * 128 + kk * 2));
            }
            uint32_t bf[8][2];
#pragma unroll
            for (int np = 0; np < 4; np++){
                int nr = wn * 64 + np * 16 + (lane & 7) + ((lane >> 4) << 3);
                int kk = kb + (((lane >> 3) & 1) << 3);
                uint32_t t0, t1, t2, t3;
                ldsm_x4(t0, t1, t2, t3, b_base + swz(nr * 128 + kk * 2));
                bf[np * 2][0] = t0;     bf[np * 2][1] = t1;
                bf[np * 2 + 1][0] = t2; bf[np * 2 + 1][1] = t3;
            }
#pragma unroll
            for (int mt = 0; mt < 2; mt++)
#pragma unroll
                for (int nt = 0; nt < 8; nt++)
                    mma16816(acc[mt][nt], af[mt][0], af[mt][1], af[mt][2], af[mt][3],
                             bf[nt][0], bf[nt][1]);
        }
        __syncthreads();
        if (c + 2 < 8) load_chunk(st, c + 2);
    }

    int bi = g_bestidx[row0 >> 13];
    if (tid < 128) sbias[tid] = b2[col0 + tid];
    else if (tid < 256) semb[tid - 128] = emb[(size_t)bi * D + col0 + tid - 128];
    __syncthreads();

    const int part = (blockIdx.x * 2 + wn) * MTOK;   // unique per (colblk, n-half)
#pragma unroll
    for (int mt = 0; mt < 2; mt++){
#pragma unroll
        for (int h2 = 0; h2 < 2; h2++){
            int gm = row0 + wm * 32 + mt * 16 + (lane >> 2) + h2 * 8;
            float ls = 0.f, ld = 0.f, lx = 0.f;
#pragma unroll
            for (int nt = 0; nt < 8; nt++){
                int ln = wn * 64 + nt * 8 + (lane & 3) * 2;
                float2 xv = *(const float2*)(x + (size_t)gm * D + col0 + ln);
                float p0 = acc[mt][nt][h2 * 2 + 0] + sbias[ln];
                float p1 = acc[mt][nt][h2 * 2 + 1] + sbias[ln + 1];
                float d0 = xv.x - p0, d1 = xv.y - p1;
                ls = fmaf(d0, d0, fmaf(d1, d1, ls));
                ld = fmaf(xv.x, semb[ln], fmaf(xv.y, semb[ln + 1], ld));
                lx = fmaf(xv.x, xv.x, fmaf(xv.y, xv.y, lx));
            }
            ls += __shfl_xor_sync(0xffffffffu, ls, 1);
            ls += __shfl_xor_sync(0xffffffffu, ls, 2);
            ld += __shfl_xor_sync(0xffffffffu, ld, 1);
            ld += __shfl_xor_sync(0xffffffffu, ld, 2);
            lx += __shfl_xor_sync(0xffffffffu, lx, 1);
            lx += __shfl_xor_sync(0xffffffffu, lx, 2);
            if ((lane & 3) == 0){
                g_sseP[part + gm] = ls;
                g_dtP[part + gm]  = ld;
                g_xnP[part + gm]  = lx;
            }
        }
    }
}

// ---------------- final: combine 8 partials per row -> surprise --------------
__global__ void surprise_final_kernel(float* __restrict__ out){
    int row = blockIdx.x * 256 + threadIdx.x;  // grid 256
    int b = row >> 13;
    float sse = 0.f, dt = 0.f, xn = 0.f;
#pragma unroll
    for (int p = 0; p < 8; p++){
        sse += g_sseP[p * MTOK + row];
        dt  += g_dtP[p * MTOK + row];
        xn  += g_xnP[p * MTOK + row];
    }
    float ps = sqrtf(sse * (1.0f / 512.0f));
    float na = fmaxf(sqrtf(xn), 1e-8f);
    float dv = 1.0f - dt / (na * g_bsnorm[b]);
    out[row] = fmaxf(ps, g_gate[b] * dv);
}

// ---------------- launch (R12 structure: serial main chain, side forks) ------
extern "C" void kernel_launch(void* const* d_in, const int* in_sizes, int n_in,
                              void* d_out, int out_size){
    const float* x  = (const float*)d_in[0];
    const float* Wc = (const float*)d_in[1];
    const float* bc = (const float*)d_in[2];
    const float* W1 = (const float*)d_in[3];
    const float* b1 = (const float*)d_in[4];
    const float* W2 = (const float*)d_in[5];
    const float* b2 = (const float*)d_in[6];
    const float* emb= (const float*)d_in[7];
    const float* act= (const float*)d_in[8];
    float* out = (float*)d_out;
    const int S = in_sizes[8];        // 131072
    const int M = in_sizes[0] / D;    // 65536 tokens

    __nv_bfloat16 *pCtx, *pHb, *pW1b, *pWcTb, *pWfb, *pW2b;
    float* pbf;
    cudaGetSymbolAddress((void**)&pCtx,  g_ctx);
    cudaGetSymbolAddress((void**)&pHb,   g_hb);
    cudaGetSymbolAddress((void**)&pW1b,  g_W1b);
    cudaGetSymbolAddress((void**)&pWcTb, g_WcTb);
    cudaGetSymbolAddress((void**)&pWfb,  g_Wfb);
    cudaGetSymbolAddress((void**)&pW2b,  g_W2b);
    cudaGetSymbolAddress((void**)&pbf,   g_bf);

    const int GSMEM = 65536;  // 2 stages x (16KB A + 16KB B)
    static bool once = false;
    static cudaStream_t sW = nullptr, sS = nullptr;
    static cudaEvent_t evStart = nullptr, evW = nullptr, evP = nullptr, evS = nullptr;
    if (!once){
        cudaFuncSetAttribute(mma_gemm_nt<0>, cudaFuncAttributeMaxDynamicSharedMemorySize, GSMEM);
        cudaFuncSetAttribute(mma_gemm_nt<1>, cudaFuncAttributeMaxDynamicSharedMemorySize, GSMEM);
        cudaFuncSetAttribute(mma_gemm2_fused, cudaFuncAttributeMaxDynamicSharedMemorySize, GSMEM);
        cudaStreamCreateWithFlags(&sW, cudaStreamNonBlocking);
        cudaStreamCreateWithFlags(&sS, cudaStreamNonBlocking);
        cudaEventCreateWithFlags(&evStart, cudaEventDisableTiming);
        cudaEventCreateWithFlags(&evW,     cudaEventDisableTiming);
        cudaEventCreateWithFlags(&evP,     cudaEventDisableTiming);
        cudaEventCreateWithFlags(&evS,     cudaEventDisableTiming);
        once = true;
    }

    init_kernel<<<1, 512>>>();
    cudaEventRecord(evStart, 0);

    // weight chain on sW: convert + transpose + Wf GEMM
    cudaStreamWaitEvent(sW, evStart, 0);
    convert_bias_kernel<<<512, 512, 0, sW>>>(W1, W2, bc, b1);
    transpose_conv_kernel<<<dim3(16, 16), dim3(32, 8), 0, sW>>>(Wc);
    mma_gemm_nt<0><<<dim3(4, 4), 256, GSMEM, sW>>>(pW1b, pWcTb, nullptr, pWfb); // Wf = W1@Wc
    cudaEventRecord(evW, sW);

    // main: x -> ctx + pooled (float4/uint2 version)
    conv_pool_kernel<<<dim3(8, 64), 128>>>(x);
    cudaEventRecord(evP, 0);

    // scan chain on sS
    cudaStreamWaitEvent(sS, evP, 0);
    sim_scan_kernel<<<512, 256, 0, sS>>>(emb, act, S);
    decode_kernel<<<1, 256, 0, sS>>>(emb);
    cudaEventRecord(evS, sS);

    // main: gemm1 after weights ready
    cudaStreamWaitEvent(0, evW, 0);
    mma_gemm_nt<1><<<dim3(4, M / 128), 256, GSMEM>>>(pCtx, pWfb, pbf, pHb);     // h = gelu(ctx@Wf^T+bf)

    // gemm2 needs decode results
    cudaStreamWaitEvent(0, evS, 0);
    mma_gemm2_fused<<<dim3(4, M / 128), 256, GSMEM>>>(pHb, pW2b, b2, x, emb);   // surprise partials
    surprise_final_kernel<<<M / 256, 256>>>(out);
}

// round 16
// speedup vs baseline: 1.0878x; 1.0245x over previous
#include <cuda_runtime.h>
#include <cuda_bf16.h>
#include <cstdint>
#include <cstddef>
#include <math.h>

#define D 512
#define LSEQ 8192
#define MTOK 65536

// ---------------- scratch (static __device__, no allocs) ----------------
__device__ __nv_bfloat16 g_ctx[(size_t)MTOK * D];   // 64MB shifted x, bf16
__device__ __nv_bfloat16 g_hb[(size_t)MTOK * D];    // 64MB gelu hidden, bf16
__device__ __nv_bfloat16 g_W1b[D * D];
__device__ __nv_bfloat16 g_W2b[D * D];
__device__ __nv_bfloat16 g_WcTb[D * D];
__device__ __nv_bfloat16 g_Wfb[D * D];              // bf16(W1 @ Wc)
__device__ float g_bf[D];                           // W1@bc + b1
__device__ float g_pooled[8 * D];
__device__ unsigned long long g_best[8];
__device__ float g_gate[8];
__device__ int   g_bestidx[8];
__device__ float g_bsnorm[8];
__device__ float g_sseP[8 * MTOK];                  // write-once partials per (colblk*2+wn, row)
__device__ float g_dtP[8 * MTOK];
__device__ float g_xnP[8 * MTOK];

// ---------------- helpers ----------------
__device__ __forceinline__ uint32_t smem_u32(const void* p){
    uint32_t a;
    asm("{ .reg .u64 t; cvta.to.shared.u64 t, %1; cvt.u32.u64 %0, t; }" : "=r"(a) : "l"(p));
    return a;
}
__device__ __forceinline__ uint32_t swz(uint32_t x){ return x ^ ((x >> 3) & 0x70); }
__device__ __forceinline__ void cp_async16(uint32_t dst, const void* src){
    asm volatile("cp.async.cg.shared.global [%0], [%1], 16;" :: "r"(dst), "l"(src) : "memory");
}
__device__ __forceinline__ void cp_commit(){
    asm volatile("cp.async.commit_group;" ::: "memory");
}
template<int N> __device__ __forceinline__ void cp_wait(){
    asm volatile("cp.async.wait_group %0;" :: "n"(N) : "memory");
}
__device__ __forceinline__ void ldsm_x4(uint32_t& r0, uint32_t& r1, uint32_t& r2, uint32_t& r3,
                                        uint32_t addr){
    asm volatile("ldmatrix.sync.aligned.m8n8.x4.shared.b16 {%0,%1,%2,%3}, [%4];"
                 : "=r"(r0), "=r"(r1), "=r"(r2), "=r"(r3) : "r"(addr));
}
__device__ __forceinline__ void mma16816(float* c, uint32_t a0, uint32_t a1, uint32_t a2,
                                         uint32_t a3, uint32_t b0, uint32_t b1){
    asm volatile("mma.sync.aligned.m16n8k16.row.col.f32.bf16.bf16.f32 "
                 "{%0,%1,%2,%3}, {%4,%5,%6,%7}, {%8,%9}, {%0,%1,%2,%3};"
                 : "+f"(c[0]), "+f"(c[1]), "+f"(c[2]), "+f"(c[3])
                 : "r"(a0), "r"(a1), "r"(a2), "r"(a3), "r"(b0), "r"(b1));
}
__device__ __forceinline__ float warp_sum(float v){
#pragma unroll
    for (int o = 16; o > 0; o >>= 1) v += __shfl_xor_sync(0xffffffffu, v, o);
    return v;
}
__device__ __forceinline__ float gelu_exact(float v){
    return 0.5f * v * (1.0f + erff(v * 0.70710678118654752f));
}
__device__ __forceinline__ uint32_t pack_bf2(float a, float b){
    __nv_bfloat162 h2 = __floats2bfloat162_rn(a, b);
    return *(uint32_t*)&h2;
}

// ---------------- small kernels ----------------
__global__ void init_kernel(){
    int t = threadIdx.x;  // 512
#pragma unroll
    for (int i = 0; i < 8; i++) g_pooled[t + i * 512] = 0.f;
    if (t < 8) g_best[t] = 0x007FFFFF00000000ull;
}

// W1/W2 -> bf16, fused bias bf[m] = W1[m]·bc + b1[m]
__global__ void convert_bias_kernel(const float* __restrict__ W1, const float* __restrict__ W2,
                                    const float* __restrict__ bc, const float* __restrict__ b1){
    __shared__ float red[16];
    int m = blockIdx.x, t = threadIdx.x;       // grid 512 x 512
    float v1 = W1[(size_t)m * D + t];
    g_W1b[(size_t)m * D + t] = __float2bfloat16(v1);
    g_W2b[(size_t)m * D + t] = __float2bfloat16(W2[(size_t)m * D + t]);
    float s = v1 * bc[t];
    s = warp_sum(s);
    if ((t & 31) == 0) red[t >> 5] = s;
    __syncthreads();
    if (t == 0){
        float a = 0.f;
#pragma unroll
        for (int w = 0; w < 16; w++) a += red[w];
        g_bf[m] = a + b1[m];
    }
}

__global__ void transpose_conv_kernel(const float* __restrict__ in){
    __shared__ float t[32][33];
    int bx = blockIdx.x * 32, by = blockIdx.y * 32;
    int txx = threadIdx.x, tyy = threadIdx.y;  // (32, 8)
#pragma unroll
    for (int i = 0; i < 32; i += 8)
        t[tyy + i][txx] = in[(size_t)(by + tyy + i) * D + bx + txx];
    __syncthreads();
#pragma unroll
    for (int i = 0; i < 32; i += 8)
        g_WcTb[(size_t)(bx + tyy + i) * D + by + txx] = __float2bfloat16(t[txx][tyy + i]);
}

// x -> ctx_bf16 (causal shift) + pooled sums; paired cols for full-sector stores
__global__ void conv_pool_kernel(const float* __restrict__ x){
    int b = blockIdx.x, seg = blockIdx.y;   // grid (8, 64)
    int d = threadIdx.x;                    // 256 threads; cols 2d, 2d+1
    if (seg == 0)
        *(uint32_t*)&g_ctx[(size_t)b * LSEQ * D + 2 * d] = 0u;   // ctx row 0 = 0
    const float2* xb = (const float2*)(x + ((size_t)b * LSEQ + (size_t)seg * 128) * D) + d;
    float s0 = 0.f, s1 = 0.f;
#pragma unroll 4
    for (int l = 0; l < 128; l++){
        float2 v = xb[(size_t)l * 256];
        s0 += v.x; s1 += v.y;
        int gl = seg * 128 + l;
        if (gl != LSEQ - 1)
            *(uint32_t*)&g_ctx[((size_t)b * LSEQ + gl + 1) * D + 2 * d] = pack_bf2(v.x, v.y);
    }
    atomicAdd(&g_pooled[b * D + 2 * d],     s0);
    atomicAdd(&g_pooled[b * D + 2 * d + 1], s1);
}

// ballot-driven cosine scan; pooled norms computed in-block
__global__ void sim_scan_kernel(const float* __restrict__ emb,
                                const float* __restrict__ act, int S){
    __shared__ float shp[8 * D];
    __shared__ float shn[8];
    __shared__ unsigned long long sbest[8][8];
    int tid = threadIdx.x;
    for (int i = tid; i < 8 * D; i += 256) shp[i] = g_pooled[i];
    __syncthreads();
    int warp = tid >> 5, lane = tid & 31;
    {   // warp w -> pooled norm of batch w
        float s = 0.f;
#pragma unroll
        for (int j = 0; j < 16; j++){ float v = shp[warp * D + lane + j * 32]; s = fmaf(v, v, s); }
        s = warp_sum(s);
        if (lane == 0) shn[warp] = fmaxf(sqrtf(s), 1e-8f);
    }
    __syncthreads();
    int s0 = (blockIdx.x * 8 + warp) * 32;   // grid 512 x 8 warps x 32 = 131072
    unsigned long long best[8];
#pragma unroll
    for (int b = 0; b < 8; b++) best[b] = 0x007FFFFF00000000ull;

    float av = (s0 + lane < S) ? act[s0 + lane] : 0.f;
    unsigned msk = __ballot_sync(0xffffffffu, av > 0.f);
    while (msk){
        int i = __ffs(msk) - 1; msk &= msk - 1;
        int s = s0 + i;
        const float* er = emb + (size_t)s * D;
        float acc[8] = {0,0,0,0,0,0,0,0};
        float nn = 0.f;
#pragma unroll
        for (int jj = 0; jj < 16; jj++){
            int d = lane + jj * 32;
            float e = er[d];
            nn = fmaf(e, e, nn);
#pragma unroll
            for (int b = 0; b < 8; b++) acc[b] = fmaf(e, shp[b * D + d], acc[b]);
        }
        nn = warp_sum(nn);
#pragma unroll
        for (int b = 0; b < 8; b++) acc[b] = warp_sum(acc[b]);
        if (lane == 0){
            float ne = fmaxf(sqrtf(nn), 1e-8f);
#pragma unroll
            for (int b = 0; b < 8; b++){
                float sim = acc[b] / (shn[b] * ne);
                unsigned u = __float_as_uint(sim);
                unsigned en = (u & 0x80000000u) ? ~u : (u | 0x80000000u);
                unsigned long long p = ((unsigned long long)en << 32)
                                     | (unsigned)(0xFFFFFFFFu - (unsigned)s);
                if (p > best[b]) best[b] = p;
            }
        }
    }
    if (lane == 0){
#pragma unroll
        for (int b = 0; b < 8; b++) sbest[warp][b] = best[b];
    }
    __syncthreads();
    if (tid < 8){
        unsigned long long m = sbest[0][tid];
#pragma unroll
        for (int w = 1; w < 8; w++) if (sbest[w][tid] > m) m = sbest[w][tid];
        atomicMax(&g_best[tid], m);
    }
}

__global__ void decode_kernel(const float* __restrict__ emb){
    __shared__ int sidx[8];
    int tid = threadIdx.x;  // 256
    if (tid < 8){
        unsigned long long p = g_best[tid];
        unsigned en = (unsigned)(p >> 32);
        unsigned u = (en & 0x80000000u) ? (en & 0x7FFFFFFFu) : ~en;
        float ms = __uint_as_float(u);
        int idx = (int)(0xFFFFFFFFu - (unsigned)p);
        if (!(ms > -INFINITY)) idx = 0;
        sidx[tid] = idx;
        g_bestidx[tid] = idx;
        g_gate[tid] = (ms > 0.3f) ? 2.0f : 0.0f;
    }
    __syncthreads();
    int warp = tid >> 5, lane = tid & 31;
    const float* er = emb + (size_t)sidx[warp] * D;
    float s = 0.f;
    for (int j = lane; j < D; j += 32){ float v = er[j]; s += v * v; }
    s = warp_sum(s);
    if (lane == 0) g_bsnorm[warp] = fmaxf(sqrtf(s), 1e-8f);
}

// ---------------- HMMA NT GEMM, 3-stage ring (one barrier per K-chunk) --------
// C[m][n] = sum_k A[m][k]*B[n][k];  MODE 0: plain->bf16   MODE 1: gelu(.+bias)->bf16
template<int MODE>
__global__ void __launch_bounds__(256, 2) mma_gemm_nt(
    const __nv_bfloat16* __restrict__ A, const __nv_bfloat16* __restrict__ B,
    const float* __restrict__ bias, __nv_bfloat16* __restrict__ C)
{
    extern __shared__ __align__(1024) char smem[];
    __shared__ float sbias[128];
    const int tid = threadIdx.x;
    const int wid = tid >> 5, lane = tid & 31;
    const int row0 = blockIdx.y * 128, col0 = blockIdx.x * 128;
    const int wm = wid & 3, wn = wid >> 2;
    uint32_t sb = smem_u32(smem);
    // stage st (3 stages x 32KB): A at st*32768, B at st*32768 + 16384

    auto load_chunk = [&](int st, int c){
        int k0 = c * 64;
        uint32_t ab = sb + st * 32768;
        uint32_t bb = ab + 16384;
#pragma unroll
        for (int i = 0; i < 4; i++){
            int lin = tid + i * 256;
            int r = lin >> 3, sg = lin & 7;
            cp_async16(ab + swz(r * 128 + sg * 16),
                       A + (size_t)(row0 + r) * D + k0 + sg * 8);
        }
#pragma unroll
        for (int i = 0; i < 4; i++){
            int lin = tid + i * 256;
            int r = lin >> 3, sg = lin & 7;
            cp_async16(bb + swz(r * 128 + sg * 16),
                       B + (size_t)(col0 + r) * D + k0 + sg * 8);
        }
        cp_commit();
    };

    load_chunk(0, 0);
    load_chunk(1, 1);

    float acc[2][8][4];
#pragma unroll
    for (int mt = 0; mt < 2; mt++)
#pragma unroll
        for (int nt = 0; nt < 8; nt++)
#pragma unroll
            for (int q = 0; q < 4; q++) acc[mt][nt][q] = 0.f;

    for (int c = 0; c < 8; c++){
        int st = c % 3;
        if (c < 7) cp_wait<1>(); else cp_wait<0>();
        __syncthreads();                       // chunk c ready; all warps done with c-1
        if (c + 2 < 8) load_chunk((c + 2) % 3, c + 2);   // refill stage read at c-1
        uint32_t a_base = sb + st * 32768;
        uint32_t b_base = a_base + 16384;
#pragma unroll
        for (int ks = 0; ks < 4; ks++){
            int kb = ks * 16;
            uint32_t af[2][4];
#pragma unroll
            for (int mt = 0; mt < 2; mt++){
                int r  = wm * 32 + mt * 16 + (lane & 15);
                int kk = kb + ((lane >> 4) << 3);
                ldsm_x4(af[mt][0], af[mt][1], af[mt][2], af[mt][3],
                        a_base + swz(r * 128 + kk * 2));
            }
            uint32_t bf[8][2];
#pragma unroll
            for (int np = 0; np < 4; np++){
                int nr = wn * 64 + np * 16 + (lane & 7) + ((lane >> 4) << 3);
                int kk = kb + (((lane >> 3) & 1) << 3);
                uint32_t t0, t1, t2, t3;
                ldsm_x4(t0, t1, t2, t3, b_base + swz(nr * 128 + kk * 2));
                bf[np * 2][0] = t0;     bf[np * 2][1] = t1;
                bf[np * 2 + 1][0] = t2; bf[np * 2 + 1][1] = t3;
            }
#pragma unroll
            for (int mt = 0; mt < 2; mt++)
#pragma unroll
                for (int nt = 0; nt < 8; nt++)
                    mma16816(acc[mt][nt], af[mt][0], af[mt][1], af[mt][2], af[mt][3],
                             bf[nt][0], bf[nt][1]);
        }
    }

    if (MODE >= 1){
        if (tid < 128) sbias[tid] = bias[col0 + tid];
        __syncthreads();
    }

#pragma unroll
    for (int mt = 0; mt < 2; mt++){
        int gm0 = row0 + wm * 32 + mt * 16 + (lane >> 2);
#pragma unroll
        for (int nt = 0; nt < 8; nt++){
            int ln = wn * 64 + nt * 8 + (lane & 3) * 2;
            int gn = col0 + ln;
            float v0 = acc[mt][nt][0], v1 = acc[mt][nt][1];
            float v2 = acc[mt][nt][2], v3 = acc[mt][nt][3];
            if (MODE >= 1){
                float b0v = sbias[ln], b1v = sbias[ln + 1];
                v0 += b0v; v1 += b1v; v2 += b0v; v3 += b1v;
            }
            if (MODE == 1){
                v0 = gelu_exact(v0); v1 = gelu_exact(v1);
                v2 = gelu_exact(v2); v3 = gelu_exact(v3);
            }
            *(uint32_t*)(C + (size_t)gm0 * D + gn)       = pack_bf2(v0, v1);
            *(uint32_t*)(C + (size_t)(gm0 + 8) * D + gn) = pack_bf2(v2, v3);
        }
    }
}

// ---------------- GEMM2 fused (3-stage ring): pred consumed in-register -------
// epilogue: write-once per-(colblk, n-half) row partials — no atomics, no pre-zero
__global__ void __launch_bounds__(256, 2) mma_gemm2_fused(
    const __nv_bfloat16* __restrict__ A, const __nv_bfloat16* __restrict__ B,
    const float* __restrict__ b2, const float* __restrict__ x,
    const float* __restrict__ emb)
{
    extern __shared__ __align__(1024) char smem[];
    __shared__ float sbias[128];
    __shared__ float semb[128];
    const int tid = threadIdx.x;
    const int wid = tid >> 5, lane = tid & 31;
    const int row0 = blockIdx.y * 128, col0 = blockIdx.x * 128;
    const int wm = wid & 3, wn = wid >> 2;
    uint32_t sb = smem_u32(smem);

    auto load_chunk = [&](int st, int c){
        int k0 = c * 64;
        uint32_t ab = sb + st * 32768;
        uint32_t bb = ab + 16384;
#pragma unroll
        for (int i = 0; i < 4; i++){
            int lin = tid + i * 256;
            int r = lin >> 3, sg = lin & 7;
            cp_async16(ab + swz(r * 128 + sg * 16),
                       A + (size_t)(row0 + r) * D + k0 + sg * 8);
        }
#pragma unroll
        for (int i = 0; i < 4; i++){
            int lin = tid + i * 256;
            int r = lin >> 3, sg = lin & 7;
            cp_async16(bb + swz(r * 128 + sg * 16),
                       B + (size_t)(col0 + r) * D + k0 + sg * 8);
        }
        cp_commit();
    };

    load_chunk(0, 0);
    load_chunk(1, 1);

    float acc[2][8][4];
#pragma unroll
    for (int mt = 0; mt < 2; mt++)
#pragma unroll
        for (int nt = 0; nt < 8; nt++)
#pragma unroll
            for (int q = 0; q < 4; q++) acc[mt][nt][q] = 0.f;

    for (int c = 0; c < 8; c++){
        int st = c % 3;
        if (c < 7) cp_wait<1>(); else cp_wait<0>();
        __syncthreads();
        if (c + 2 < 8) load_chunk((c + 2) % 3, c + 2);
        uint32_t a_base = sb + st * 32768;
        uint32_t b_base = a_base + 16384;
#pragma unroll
        for (int ks = 0; ks < 4; ks++){
            int kb = ks * 16;
            uint32_t af[2][4];
#pragma unroll
            for (int mt = 0; mt < 2; mt++){
                int r  = wm * 32 + mt * 16 + (lane & 15);
                int kk = kb + ((lane >> 4) << 3);
                ldsm_x4(af[mt][0], af[mt][1], af[mt][2], af[mt][3],
                        a_base + swz(r * 128 + kk * 2));
            }
            uint32_t bf[8][2];
#pragma unroll
            for (int np = 0; np < 4; np++){
                int nr = wn * 64 + np * 16 + (lane & 7) + ((lane >> 4) << 3);
                int kk = kb + (((lane >> 3) & 1) << 3);
                uint32_t t0, t1, t2, t3;
                ldsm_x4(t0, t1, t2, t3, b_base + swz(nr * 128 + kk * 2));
                bf[np * 2][0] = t0;     bf[np * 2][1] = t1;
                bf[np * 2 + 1][0] = t2; bf[np * 2 + 1][1] = t3;
            }
#pragma unroll
            for (int mt = 0; mt < 2; mt++)
#pragma unroll
                for (int nt = 0; nt < 8; nt++)
                    mma16816(acc[mt][nt], af[mt][0], af[mt][1], af[mt][2], af[mt][3],
                             bf[nt][0], bf[nt][1]);
        }
    }

    int bi = g_bestidx[row0 >> 13];
    if (tid < 128) sbias[tid] = b2[col0 + tid];
    else if (tid < 256) semb[tid - 128] = emb[(size_t)bi * D + col0 + tid - 128];
    __syncthreads();

    const int part = (blockIdx.x * 2 + wn) * MTOK;   // unique per (colblk, n-half)
#pragma unroll
    for (int mt = 0; mt < 2; mt++){
#pragma unroll
        for (int h2 = 0; h2 < 2; h2++){
            int gm = row0 + wm * 32 + mt * 16 + (lane >> 2) + h2 * 8;
            float ls = 0.f, ld = 0.f, lx = 0.f;
#pragma unroll
            for (int nt = 0; nt < 8; nt++){
                int ln = wn * 64 + nt * 8 + (lane & 3) * 2;
                float2 xv = *(const float2*)(x + (size_t)gm * D + col0 + ln);
                float p0 = acc[mt][nt][h2 * 2 + 0] + sbias[ln];
                float p1 = acc[mt][nt][h2 * 2 + 1] + sbias[ln + 1];
                float d0 = xv.x - p0, d1 = xv.y - p1;
                ls = fmaf(d0, d0, fmaf(d1, d1, ls));
                ld = fmaf(xv.x, semb[ln], fmaf(xv.y, semb[ln + 1], ld));
                lx = fmaf(xv.x, xv.x, fmaf(xv.y, xv.y, lx));
            }
            ls += __shfl_xor_sync(0xffffffffu, ls, 1);
            ls += __shfl_xor_sync(0xffffffffu, ls, 2);
            ld += __shfl_xor_sync(0xffffffffu, ld, 1);
            ld += __shfl_xor_sync(0xffffffffu, ld, 2);
            lx += __shfl_xor_sync(0xffffffffu, lx, 1);
            lx += __shfl_xor_sync(0xffffffffu, lx, 2);
            if ((lane & 3) == 0){
                g_sseP[part + gm] = ls;
                g_dtP[part + gm]  = ld;
                g_xnP[part + gm]  = lx;
            }
        }
    }
}

// ---------------- final: combine 8 partials per row -> surprise --------------
__global__ void surprise_final_kernel(float* __restrict__ out){
    int row = blockIdx.x * 256 + threadIdx.x;  // grid 256
    int b = row >> 13;
    float sse = 0.f, dt = 0.f, xn = 0.f;
#pragma unroll
    for (int p = 0; p < 8; p++){
        sse += g_sseP[p * MTOK + row];
        dt  += g_dtP[p * MTOK + row];
        xn  += g_xnP[p * MTOK + row];
    }
    float ps = sqrtf(sse * (1.0f / 512.0f));
    float na = fmaxf(sqrtf(xn), 1e-8f);
    float dv = 1.0f - dt / (na * g_bsnorm[b]);
    out[row] = fmaxf(ps, g_gate[b] * dv);
}

// ---------------- launch (R12 structure: serial main chain, side forks) ------
extern "C" void kernel_launch(void* const* d_in, const int* in_sizes, int n_in,
                              void* d_out, int out_size){
    const float* x  = (const float*)d_in[0];
    const float* Wc = (const float*)d_in[1];
    const float* bc = (const float*)d_in[2];
    const float* W1 = (const float*)d_in[3];
    const float* b1 = (const float*)d_in[4];
    const float* W2 = (const float*)d_in[5];
    const float* b2 = (const float*)d_in[6];
    const float* emb= (const float*)d_in[7];
    const float* act= (const float*)d_in[8];
    float* out = (float*)d_out;
    const int S = in_sizes[8];        // 131072
    const int M = in_sizes[0] / D;    // 65536 tokens

    __nv_bfloat16 *pCtx, *pHb, *pW1b, *pWcTb, *pWfb, *pW2b;
    float* pbf;
    cudaGetSymbolAddress((void**)&pCtx,  g_ctx);
    cudaGetSymbolAddress((void**)&pHb,   g_hb);
    cudaGetSymbolAddress((void**)&pW1b,  g_W1b);
    cudaGetSymbolAddress((void**)&pWcTb, g_WcTb);
    cudaGetSymbolAddress((void**)&pWfb,  g_Wfb);
    cudaGetSymbolAddress((void**)&pW2b,  g_W2b);
    cudaGetSymbolAddress((void**)&pbf,   g_bf);

    const int GSMEM = 98304;  // 3 stages x (16KB A + 16KB B)
    static bool once = false;
    static cudaStream_t sW = nullptr, sS = nullptr;
    static cudaEvent_t evStart = nullptr, evW = nullptr, evP = nullptr, evS = nullptr;
    if (!once){
        cudaFuncSetAttribute(mma_gemm_nt<0>, cudaFuncAttributeMaxDynamicSharedMemorySize, GSMEM);
        cudaFuncSetAttribute(mma_gemm_nt<1>, cudaFuncAttributeMaxDynamicSharedMemorySize, GSMEM);
        cudaFuncSetAttribute(mma_gemm2_fused, cudaFuncAttributeMaxDynamicSharedMemorySize, GSMEM);
        cudaStreamCreateWithFlags(&sW, cudaStreamNonBlocking);
        cudaStreamCreateWithFlags(&sS, cudaStreamNonBlocking);
        cudaEventCreateWithFlags(&evStart, cudaEventDisableTiming);
        cudaEventCreateWithFlags(&evW,     cudaEventDisableTiming);
        cudaEventCreateWithFlags(&evP,     cudaEventDisableTiming);
        cudaEventCreateWithFlags(&evS,     cudaEventDisableTiming);
        once = true;
    }

    init_kernel<<<1, 512>>>();
    cudaEventRecord(evStart, 0);

    // weight chain on sW: convert + transpose + Wf GEMM
    cudaStreamWaitEvent(sW, evStart, 0);
    convert_bias_kernel<<<512, 512, 0, sW>>>(W1, W2, bc, b1);
    transpose_conv_kernel<<<dim3(16, 16), dim3(32, 8), 0, sW>>>(Wc);
    mma_gemm_nt<0><<<dim3(4, 4), 256, GSMEM, sW>>>(pW1b, pWcTb, nullptr, pWfb); // Wf = W1@Wc
    cudaEventRecord(evW, sW);

    // main: x -> ctx + pooled
    conv_pool_kernel<<<dim3(8, 64), 256>>>(x);
    cudaEventRecord(evP, 0);

    // scan chain on sS
    cudaStreamWaitEvent(sS, evP, 0);
    sim_scan_kernel<<<512, 256, 0, sS>>>(emb, act, S);
    decode_kernel<<<1, 256, 0, sS>>>(emb);
    cudaEventRecord(evS, sS);

    // main: gemm1 after weights ready
    cudaStreamWaitEvent(0, evW, 0);
    mma_gemm_nt<1><<<dim3(4, M / 128), 256, GSMEM>>>(pCtx, pWfb, pbf, pHb);     // h = gelu(ctx@Wf^T+bf)

    // gemm2 needs decode results
    cudaStreamWaitEvent(0, evS, 0);
    mma_gemm2_fused<<<dim3(4, M / 128), 256, GSMEM>>>(pHb, pW2b, b2, x, emb);   // surprise partials
    surprise_final_kernel<<<M / 256, 256>>>(out);
}